// round 8
// baseline (speedup 1.0000x reference)
#include <cuda_runtime.h>
#include <cuda_bf16.h>
#include <cstdint>
#include <math.h>

#define NB 8
#define NC 512
#define ND 256
#define NT 2048

// ---------------- scratch (device globals; no allocations allowed) ----------
__device__ float g_thT [(size_t)NB * NT * ND];   // theta^T  (B,T,D)
__device__ float g_phT [(size_t)NB * NT * ND];   // phi^T    (B,T,D)
__device__ float g_g   [(size_t)NB * ND * NT];   // g        (B,D,T)
__device__ float g_W   [(size_t)NB * NT * NT];   // W / P    (B,T,S)
__device__ float g_atT [(size_t)NB * NT * ND];   // attn^T   (B,S,D)
__device__ float g_h   [(size_t)NB * NC * NT];   // h        (B,C,T)
__device__ float g_mean[NC];
__device__ float g_istd[NC];

// ---------------- helpers ----------------------------------------------------
// bf16x3 split: x = hi + lo (each bf16 RN); packs pairs (x low half, y high half)
__device__ __forceinline__ void split2(float x, float y, uint32_t& hi, uint32_t& lo) {
    __nv_bfloat162 h = __floats2bfloat162_rn(x, y);
    float hx = __low2float(h), hy = __high2float(h);
    __nv_bfloat162 l = __floats2bfloat162_rn(x - hx, y - hy);
    hi = *reinterpret_cast<uint32_t*>(&h);
    lo = *reinterpret_cast<uint32_t*>(&l);
}

__device__ __forceinline__ void mma16(float* d, const uint32_t* a, const uint32_t* b) {
    asm volatile(
        "mma.sync.aligned.m16n8k16.row.col.f32.bf16.bf16.f32 "
        "{%0,%1,%2,%3}, {%4,%5,%6,%7}, {%8,%9}, {%0,%1,%2,%3};"
        : "+f"(d[0]), "+f"(d[1]), "+f"(d[2]), "+f"(d[3])
        : "r"(a[0]), "r"(a[1]), "r"(a[2]), "r"(a[3]), "r"(b[0]), "r"(b[1]));
}

// SMEM geometry (fragment-permuted, bf16 pair-packed uint32 words)
// A plane: 16 slots (mf0..7 x ks0..1), slot = 32 lanes * 4 words, stride 132
// B plane: 32 slots (nf0..15 x ks0..1), slot = 32 lanes * 2 words, stride 68
#define A_PLANE 2112            // 16*132 words
#define B_PLANE 2176            // 32*68 words
#define BUF_WORDS (2*A_PLANE + 2*B_PLANE)   // 8576 (Ahi, Alo, Bhi, Blo)
static constexpr int SMEM_BYTES = 2 * BUF_WORDS * 4;   // 68608

// ---------------- bf16x3 mma.sync batched GEMM -------------------------------
// A natural (M,K) row-major.
// TB=false: B natural (N,K). TB=true: B is (K,N) (B[n][k] = Bg[k*ldb+n]).
// TOUT=false: C (M,N) ldc. TOUT=true: C[n*ldc + m]. Bias per-m.
template <bool TB, bool TOUT, bool BIAS>
__global__ __launch_bounds__(256, 2) void tgemm(
    const float* __restrict__ A, const float* __restrict__ B, float* __restrict__ C,
    const float* __restrict__ bias, int K, int lda, int ldb, int ldc,
    long long sA, long long sB, long long sC)
{
    extern __shared__ uint32_t sm[];
    const int tid = threadIdx.x;
    const int lane = tid & 31;
    const int wid = tid >> 5;
    const int warpM = wid >> 2, warpN = wid & 3;   // 2 x 4 warp grid
    const int g4 = lane >> 2, tig = lane & 3;
    const int bz = blockIdx.z;
    const int m0 = blockIdx.y * 128, n0 = blockIdx.x * 128;
    A += (long long)bz * sA;
    B += (long long)bz * sB;
    C += (long long)bz * sC;

    const int w_row = tid >> 3;       // 0..31
    const int w_q   = tid & 7;        // k-quad index

    float acc[4][4][4];
#pragma unroll
    for (int a = 0; a < 4; a++)
#pragma unroll
        for (int b = 0; b < 4; b++)
#pragma unroll
            for (int c = 0; c < 4; c++) acc[a][b][c] = 0.f;

    const int nch = K >> 5;
    float4 pa[4];
    float4 pb[4];
    float  pbt[16];

    // ---- global loads into registers ----
    auto ldgA = [&](int ch) {
        const float* Ag = A + (size_t)m0 * lda + ch * 32 + w_q * 4;
#pragma unroll
        for (int i = 0; i < 4; i++)
            pa[i] = *(const float4*)(Ag + (size_t)(w_row + i * 32) * lda);
    };
    auto ldgB = [&](int ch) {
        if (TB) {
            const float* Bg = B + (size_t)(ch * 32) * ldb + n0 + (tid & 127);
            const int kq0 = tid >> 7;
#pragma unroll
            for (int i = 0; i < 4; i++) {
                const float* p = Bg + (size_t)((kq0 + 2 * i) * 4) * ldb;
                pbt[i * 4 + 0] = p[0];
                pbt[i * 4 + 1] = p[(size_t)ldb];
                pbt[i * 4 + 2] = p[2 * (size_t)ldb];
                pbt[i * 4 + 3] = p[3 * (size_t)ldb];
            }
        } else {
            const float* Bg = B + (size_t)n0 * ldb + ch * 32 + w_q * 4;
#pragma unroll
            for (int i = 0; i < 4; i++)
                pb[i] = *(const float4*)(Bg + (size_t)(w_row + i * 32) * ldb);
        }
    };

    // ---- registers -> split bf16 planes in permuted SMEM ----
    auto stsTile = [&](int buf) {
        uint32_t* Ah = sm + buf * BUF_WORDS;
        uint32_t* Al = Ah + A_PLANE;
        uint32_t* Bh = Ah + 2 * A_PLANE;
        uint32_t* Bl = Bh + B_PLANE;
        // A (natural rows)
#pragma unroll
        for (int i = 0; i < 4; i++) {
            const int row = w_row + i * 32;
            const int mf = row >> 4, rm = row & 15, ks = w_q >> 2;
            const int p0 = (2 * w_q) & 7, half = p0 >> 2, pl = p0 & 3;
            const int rg = half * 2 + (rm >> 3);
            const int w0 = (mf * 2 + ks) * 132 + ((rm & 7) * 4 + pl) * 4 + rg;
            uint32_t h0, l0, h1, l1;
            split2(pa[i].x, pa[i].y, h0, l0);
            split2(pa[i].z, pa[i].w, h1, l1);
            Ah[w0] = h0; Ah[w0 + 4] = h1;
            Al[w0] = l0; Al[w0 + 4] = l1;
        }
        // B
        if (TB) {
            const int n = tid & 127;
            const int kq0 = tid >> 7;
            const int nf = n >> 3, g = n & 7;
#pragma unroll
            for (int i = 0; i < 4; i++) {
                const int q = kq0 + 2 * i;
                const int ks = q >> 2, p0 = (2 * q) & 7, half = p0 >> 2, pl = p0 & 3;
                const int w0 = (nf * 2 + ks) * 68 + (g * 4 + pl) * 2 + half;
                uint32_t h0, l0, h1, l1;
                split2(pbt[i * 4 + 0], pbt[i * 4 + 1], h0, l0);
                split2(pbt[i * 4 + 2], pbt[i * 4 + 3], h1, l1);
                Bh[w0] = h0; Bh[w0 + 2] = h1;
                Bl[w0] = l0; Bl[w0 + 2] = l1;
            }
        } else {
#pragma unroll
            for (int i = 0; i < 4; i++) {
                const int n = w_row + i * 32;
                const int nf = n >> 3, g = n & 7, ks = w_q >> 2;
                const int p0 = (2 * w_q) & 7, half = p0 >> 2, pl = p0 & 3;
                const int w0 = (nf * 2 + ks) * 68 + (g * 4 + pl) * 2 + half;
                uint32_t h0, l0, h1, l1;
                split2(pb[i].x, pb[i].y, h0, l0);
                split2(pb[i].z, pb[i].w, h1, l1);
                Bh[w0] = h0; Bh[w0 + 2] = h1;
                Bl[w0] = l0; Bl[w0 + 2] = l1;
            }
        }
    };

    // ---- compute one 32-k chunk: terms hi*hi + lo*hi + hi*lo ----
    auto compute = [&](int buf) {
        const uint32_t* Ah = sm + buf * BUF_WORDS;
        const uint32_t* Al = Ah + A_PLANE;
        const uint32_t* Bh = Ah + 2 * A_PLANE;
        const uint32_t* Bl = Bh + B_PLANE;
#pragma unroll
        for (int ks = 0; ks < 2; ks++) {
            uint32_t afh[4][4], bfh[4][2];
#pragma unroll
            for (int mf = 0; mf < 4; mf++)
                *(uint4*)afh[mf] = *(const uint4*)(Ah + ((warpM * 4 + mf) * 2 + ks) * 132 + lane * 4);
#pragma unroll
            for (int nf = 0; nf < 4; nf++)
                *(uint2*)bfh[nf] = *(const uint2*)(Bh + ((warpN * 4 + nf) * 2 + ks) * 68 + lane * 2);
            // term 1: hiA * hiB
#pragma unroll
            for (int mf = 0; mf < 4; mf++)
#pragma unroll
                for (int nf = 0; nf < 4; nf++)
                    mma16(acc[mf][nf], afh[mf], bfh[nf]);
            // term 2: loA * hiB (loA fragments loaded transiently)
#pragma unroll
            for (int mf = 0; mf < 4; mf++) {
                uint32_t t[4];
                *(uint4*)t = *(const uint4*)(Al + ((warpM * 4 + mf) * 2 + ks) * 132 + lane * 4);
#pragma unroll
                for (int nf = 0; nf < 4; nf++)
                    mma16(acc[mf][nf], t, bfh[nf]);
            }
            // term 3: hiA * loB
#pragma unroll
            for (int nf = 0; nf < 4; nf++) {
                uint32_t t[2];
                *(uint2*)t = *(const uint2*)(Bl + ((warpN * 4 + nf) * 2 + ks) * 68 + lane * 2);
#pragma unroll
                for (int mf = 0; mf < 4; mf++)
                    mma16(acc[mf][nf], afh[mf], t);
            }
        }
    };

    // ---- pipelined loop ----
    ldgA(0); ldgB(0);
    stsTile(0);
    __syncthreads();
    for (int ch = 0; ch < nch; ch++) {
        if (ch + 1 < nch) { ldgA(ch + 1); ldgB(ch + 1); }
        compute(ch & 1);
        __syncthreads();
        if (ch + 1 < nch) {
            stsTile((ch + 1) & 1);
            __syncthreads();
        }
    }

    // ---- epilogue: direct stores ----
#pragma unroll
    for (int mf = 0; mf < 4; mf++) {
        const int m = m0 + warpM * 64 + mf * 16 + g4;
        const float bv0 = BIAS ? bias[m] : 0.f;
        const float bv1 = BIAS ? bias[m + 8] : 0.f;
#pragma unroll
        for (int nf = 0; nf < 4; nf++) {
            const int n = n0 + warpN * 32 + nf * 8 + 2 * tig;
            if (TOUT) {
                C[(size_t)n * ldc + m]           = acc[mf][nf][0] + bv0;
                C[(size_t)(n + 1) * ldc + m]     = acc[mf][nf][1] + bv0;
                C[(size_t)n * ldc + m + 8]       = acc[mf][nf][2] + bv1;
                C[(size_t)(n + 1) * ldc + m + 8] = acc[mf][nf][3] + bv1;
            } else {
                *(float2*)(C + (size_t)m * ldc + n) =
                    make_float2(acc[mf][nf][0] + bv0, acc[mf][nf][1] + bv0);
                *(float2*)(C + (size_t)(m + 8) * ldc + n) =
                    make_float2(acc[mf][nf][2] + bv1, acc[mf][nf][3] + bv1);
            }
        }
    }
}

// ---------------- softmax (in place over rows of W), float4 ------------------
__global__ __launch_bounds__(256) void softmax_kernel(float* __restrict__ W)
{
    float4* p4 = (float4*)(W + (size_t)blockIdx.x * NT);
    const int t = threadIdx.x;
    float4 a = p4[t], b = p4[t + 256];
    float x[8] = {a.x, a.y, a.z, a.w, b.x, b.y, b.z, b.w};

    float m = x[0];
#pragma unroll
    for (int r = 1; r < 8; r++) m = fmaxf(m, x[r]);
#pragma unroll
    for (int o = 16; o; o >>= 1) m = fmaxf(m, __shfl_xor_sync(0xffffffffu, m, o));
    __shared__ float smax[8], ssum[8];
    if ((t & 31) == 0) smax[t >> 5] = m;
    __syncthreads();
    m = smax[0];
#pragma unroll
    for (int i = 1; i < 8; i++) m = fmaxf(m, smax[i]);
    float e[8], s = 0.f;
#pragma unroll
    for (int r = 0; r < 8; r++) { e[r] = __expf(x[r] - m); s += e[r]; }
#pragma unroll
    for (int o = 16; o; o >>= 1) s += __shfl_xor_sync(0xffffffffu, s, o);
    if ((t & 31) == 0) ssum[t >> 5] = s;
    __syncthreads();
    s = ssum[0];
#pragma unroll
    for (int i = 1; i < 8; i++) s += ssum[i];
    const float inv = 1.f / s;
    p4[t]       = make_float4(e[0] * inv, e[1] * inv, e[2] * inv, e[3] * inv);
    p4[t + 256] = make_float4(e[4] * inv, e[5] * inv, e[6] * inv, e[7] * inv);
}

// ---------------- BatchNorm stats + apply ------------------------------------
__global__ __launch_bounds__(256) void bn_stats_kernel(
    const float* __restrict__ h, float* __restrict__ mean, float* __restrict__ istd)
{
    const int c = blockIdx.x;
    float s1 = 0.f, s2 = 0.f;
    for (int i = threadIdx.x; i < NB * NT; i += 256) {
        const int b = i >> 11, t = i & (NT - 1);
        const float v = h[(size_t)b * NC * NT + (size_t)c * NT + t];
        s1 += v; s2 += v * v;
    }
#pragma unroll
    for (int o = 16; o; o >>= 1) {
        s1 += __shfl_xor_sync(0xffffffffu, s1, o);
        s2 += __shfl_xor_sync(0xffffffffu, s2, o);
    }
    __shared__ float a1[8], a2[8];
    if ((threadIdx.x & 31) == 0) { a1[threadIdx.x >> 5] = s1; a2[threadIdx.x >> 5] = s2; }
    __syncthreads();
    if (threadIdx.x == 0) {
        float t1 = 0.f, t2 = 0.f;
#pragma unroll
        for (int i = 0; i < 8; i++) { t1 += a1[i]; t2 += a2[i]; }
        const float n = (float)(NB * NT);
        const float mu = t1 / n;
        const float var = t2 / n - mu * mu;
        mean[c] = mu;
        istd[c] = rsqrtf(var + 1e-5f);
    }
}

__global__ __launch_bounds__(256) void bn_apply_kernel(
    const float* __restrict__ inpt, const float* __restrict__ h,
    const float* __restrict__ gamma, const float* __restrict__ beta,
    const float* __restrict__ mean, const float* __restrict__ istd,
    float* __restrict__ out)
{
    const int i = blockIdx.x * 256 + threadIdx.x;
    const int c = (i >> 11) & (NC - 1);
    out[i] = inpt[i] + gamma[c] * ((h[i] - mean[c]) * istd[c]) + beta[c];
}

// ---------------- launch -----------------------------------------------------
extern "C" void kernel_launch(void* const* d_in, const int* in_sizes, int n_in,
                              void* d_out, int out_size)
{
    const float* inpt    = (const float*)d_in[0];
    const float* theta_w = (const float*)d_in[1];
    const float* theta_b = (const float*)d_in[2];
    const float* phi_w   = (const float*)d_in[3];
    const float* phi_b   = (const float*)d_in[4];
    const float* gw      = (const float*)d_in[5];
    const float* gb      = (const float*)d_in[6];
    const float* ht_w    = (const float*)d_in[7];
    const float* ht_b    = (const float*)d_in[8];
    const float* bn_g    = (const float*)d_in[9];
    const float* bn_b    = (const float*)d_in[10];
    float* out = (float*)d_out;

    float *p_thT, *p_phT, *p_g, *p_W, *p_atT, *p_h, *p_mean, *p_istd;
    cudaGetSymbolAddress((void**)&p_thT, g_thT);
    cudaGetSymbolAddress((void**)&p_phT, g_phT);
    cudaGetSymbolAddress((void**)&p_g,   g_g);
    cudaGetSymbolAddress((void**)&p_W,   g_W);
    cudaGetSymbolAddress((void**)&p_atT, g_atT);
    cudaGetSymbolAddress((void**)&p_h,   g_h);
    cudaGetSymbolAddress((void**)&p_mean, g_mean);
    cudaGetSymbolAddress((void**)&p_istd, g_istd);

    cudaFuncSetAttribute(tgemm<true,  true,  true >, cudaFuncAttributeMaxDynamicSharedMemorySize, SMEM_BYTES);
    cudaFuncSetAttribute(tgemm<true,  false, true >, cudaFuncAttributeMaxDynamicSharedMemorySize, SMEM_BYTES);
    cudaFuncSetAttribute(tgemm<false, false, false>, cudaFuncAttributeMaxDynamicSharedMemorySize, SMEM_BYTES);
    cudaFuncSetAttribute(tgemm<true,  true,  false>, cudaFuncAttributeMaxDynamicSharedMemorySize, SMEM_BYTES);
    cudaFuncSetAttribute(tgemm<false, false, true >, cudaFuncAttributeMaxDynamicSharedMemorySize, SMEM_BYTES);

    const long long sTD = (long long)NT * ND;
    const long long sDT = (long long)ND * NT;
    const long long sCT = (long long)NC * NT;
    const long long sTT = (long long)NT * NT;

    // 1) theta^T, phi^T : M=D, N=T, K=C; A=weight natural, B=inpt (K,N), OUT transposed (T,D)
    {
        dim3 grid(NT / 128, ND / 128, NB);
        tgemm<true, true, true><<<grid, 256, SMEM_BYTES>>>(theta_w, inpt, p_thT, theta_b,
            NC, NC, NT, ND, 0LL, sCT, sTD);
        tgemm<true, true, true><<<grid, 256, SMEM_BYTES>>>(phi_w, inpt, p_phT, phi_b,
            NC, NC, NT, ND, 0LL, sCT, sTD);
        tgemm<true, false, true><<<grid, 256, SMEM_BYTES>>>(gw, inpt, p_g, gb,
            NC, NC, NT, NT, 0LL, sCT, sDT);
    }

    // 2) W = thT x phT^T : M=N=T, K=D; both natural, OUT natural (T,S)
    {
        dim3 grid(NT / 128, NT / 128, NB);
        tgemm<false, false, false><<<grid, 256, SMEM_BYTES>>>(p_thT, p_phT, p_W, nullptr,
            ND, ND, ND, NT, sTD, sTD, sTT);
    }

    // 3) softmax rows of W
    softmax_kernel<<<NB * NT, 256>>>(p_W);

    // 4) attn^T = (g x P)^T : M=D, N=S, K=T; A=g natural, B=P (K,N), OUT transposed (S,D)
    {
        dim3 grid(NT / 128, ND / 128, NB);
        tgemm<true, true, false><<<grid, 256, SMEM_BYTES>>>(p_g, p_W, p_atT, nullptr,
            NT, NT, NT, ND, sDT, sTT, sTD);
    }

    // 5) h = ht_w x attn : M=C, N=T, K=D; A natural, B=attn^T natural (T,D), OUT natural (C,T)
    {
        dim3 grid(NT / 128, NC / 128, NB);
        tgemm<false, false, true><<<grid, 256, SMEM_BYTES>>>(ht_w, p_atT, p_h, ht_b,
            ND, ND, ND, NT, 0LL, sTD, sCT);
    }

    // 6) BN stats + apply with residual
    bn_stats_kernel<<<NC, 256>>>(p_h, p_mean, p_istd);
    bn_apply_kernel<<<(NB * NC * NT) / 256, 256>>>(inpt, p_h, bn_g, bn_b,
                                                   p_mean, p_istd, out);
}

// round 10
// speedup vs baseline: 1.0546x; 1.0546x over previous
#include <cuda_runtime.h>
#include <cuda_bf16.h>
#include <cstdint>
#include <math.h>

#define NB 8
#define NC 512
#define ND 256
#define NT 2048

// ---------------- scratch (device globals; no allocations allowed) ----------
__device__ float g_thT [(size_t)NB * NT * ND];   // theta^T  (B,T,D)
__device__ float g_phT [(size_t)NB * NT * ND];   // phi^T    (B,T,D)
__device__ float g_g   [(size_t)NB * ND * NT];   // g        (B,D,T)
__device__ float g_W   [(size_t)NB * NT * NT];   // W / P    (B,T,S)
__device__ float g_atT [(size_t)NB * NT * ND];   // attn^T   (B,S,D)
__device__ float g_h   [(size_t)NB * NC * NT];   // h        (B,C,T)
__device__ float g_mean[NC];
__device__ float g_istd[NC];

// ---------------- helpers ----------------------------------------------------
// bf16x3 split: x = hi + lo (each bf16 RN); packs pairs (x low half, y high half)
__device__ __forceinline__ void split2(float x, float y, uint32_t& hi, uint32_t& lo) {
    __nv_bfloat162 h = __floats2bfloat162_rn(x, y);
    float hx = __low2float(h), hy = __high2float(h);
    __nv_bfloat162 l = __floats2bfloat162_rn(x - hx, y - hy);
    hi = *reinterpret_cast<uint32_t*>(&h);
    lo = *reinterpret_cast<uint32_t*>(&l);
}

__device__ __forceinline__ void mma16(float* d, const uint32_t* a, const uint32_t* b) {
    asm volatile(
        "mma.sync.aligned.m16n8k16.row.col.f32.bf16.bf16.f32 "
        "{%0,%1,%2,%3}, {%4,%5,%6,%7}, {%8,%9}, {%0,%1,%2,%3};"
        : "+f"(d[0]), "+f"(d[1]), "+f"(d[2]), "+f"(d[3])
        : "r"(a[0]), "r"(a[1]), "r"(a[2]), "r"(a[3]), "r"(b[0]), "r"(b[1]));
}

// SMEM geometry (fragment-permuted, bf16 pair-packed uint32 words)
#define A_PLANE 2112            // 16*132 words
#define B_PLANE 2176            // 32*68 words
#define BUF_WORDS (2*A_PLANE + 2*B_PLANE)   // 8576 (Ahi, Alo, Bhi, Blo)
static constexpr int SMEM_BYTES = 2 * BUF_WORDS * 4;   // 68608

// ---------------- bf16x3 mma.sync batched GEMM -------------------------------
// A natural (M,K) row-major.
// TB=false: B natural (N,K). TB=true: B is (K,N) (B[n][k] = Bg[k*ldb+n]).
// TOUT=false: C (M,N) ldc. TOUT=true: C[n*ldc + m]. Bias per-m.
// FUSED3: blockIdx.z = op*NB + b, op selects {A,C,bias}; op<2 -> TOUT(ldc=ND),
//         op==2 -> natural(ldc=NT). Used to fuse theta/phi/g projections.
template <bool TB, bool TOUT, bool BIAS, bool FUSED3>
__global__ __launch_bounds__(256, 2) void tgemm(
    const float* __restrict__ A, const float* __restrict__ B, float* __restrict__ C,
    const float* __restrict__ bias,
    const float* __restrict__ A1, float* __restrict__ C1, const float* __restrict__ bias1,
    const float* __restrict__ A2, float* __restrict__ C2, const float* __restrict__ bias2,
    int K, int lda, int ldb, int ldc,
    long long sA, long long sB, long long sC)
{
    extern __shared__ uint32_t sm[];
    const int tid = threadIdx.x;
    const int lane = tid & 31;
    const int wid = tid >> 5;
    const int warpM = wid >> 2, warpN = wid & 3;   // 2 x 4 warp grid
    const int g4 = lane >> 2, tig = lane & 3;

    int bz = blockIdx.z;
    int opsel = 0;
    if (FUSED3) {
        opsel = bz >> 3;       // 0:theta 1:phi 2:g
        bz &= 7;
        if (opsel == 1) { A = A1; C = C1; bias = bias1; }
        else if (opsel == 2) { A = A2; C = C2; bias = bias2; ldc = NT; }
    }
    const int m0 = blockIdx.y * 128, n0 = blockIdx.x * 128;
    A += (long long)bz * sA;
    B += (long long)bz * sB;
    C += (long long)bz * sC;

    const int w_row = tid >> 3;       // 0..31
    const int w_q   = tid & 7;        // k-quad index

    float acc[4][4][4];
#pragma unroll
    for (int a = 0; a < 4; a++)
#pragma unroll
        for (int b = 0; b < 4; b++)
#pragma unroll
            for (int c = 0; c < 4; c++) acc[a][b][c] = 0.f;

    const int nch = K >> 5;
    float4 pa[4];
    float4 pb[4];
    float  pbt[16];

    // ---- global loads into registers ----
    auto ldgA = [&](int ch) {
        const float* Ag = A + (size_t)m0 * lda + ch * 32 + w_q * 4;
#pragma unroll
        for (int i = 0; i < 4; i++)
            pa[i] = *(const float4*)(Ag + (size_t)(w_row + i * 32) * lda);
    };
    auto ldgB = [&](int ch) {
        if (TB) {
            const float* Bg = B + (size_t)(ch * 32) * ldb + n0 + (tid & 127);
            const int kq0 = tid >> 7;
#pragma unroll
            for (int i = 0; i < 4; i++) {
                const float* p = Bg + (size_t)((kq0 + 2 * i) * 4) * ldb;
                pbt[i * 4 + 0] = p[0];
                pbt[i * 4 + 1] = p[(size_t)ldb];
                pbt[i * 4 + 2] = p[2 * (size_t)ldb];
                pbt[i * 4 + 3] = p[3 * (size_t)ldb];
            }
        } else {
            const float* Bg = B + (size_t)n0 * ldb + ch * 32 + w_q * 4;
#pragma unroll
            for (int i = 0; i < 4; i++)
                pb[i] = *(const float4*)(Bg + (size_t)(w_row + i * 32) * ldb);
        }
    };

    // ---- registers -> split bf16 planes in permuted SMEM ----
    auto stsTile = [&](int buf) {
        uint32_t* Ah = sm + buf * BUF_WORDS;
        uint32_t* Al = Ah + A_PLANE;
        uint32_t* Bh = Ah + 2 * A_PLANE;
        uint32_t* Bl = Bh + B_PLANE;
#pragma unroll
        for (int i = 0; i < 4; i++) {
            const int row = w_row + i * 32;
            const int mf = row >> 4, rm = row & 15, ks = w_q >> 2;
            const int p0 = (2 * w_q) & 7, half = p0 >> 2, pl = p0 & 3;
            const int rg = half * 2 + (rm >> 3);
            const int w0 = (mf * 2 + ks) * 132 + ((rm & 7) * 4 + pl) * 4 + rg;
            uint32_t h0, l0, h1, l1;
            split2(pa[i].x, pa[i].y, h0, l0);
            split2(pa[i].z, pa[i].w, h1, l1);
            Ah[w0] = h0; Ah[w0 + 4] = h1;
            Al[w0] = l0; Al[w0 + 4] = l1;
        }
        if (TB) {
            const int n = tid & 127;
            const int kq0 = tid >> 7;
            const int nf = n >> 3, g = n & 7;
#pragma unroll
            for (int i = 0; i < 4; i++) {
                const int q = kq0 + 2 * i;
                const int ks = q >> 2, p0 = (2 * q) & 7, half = p0 >> 2, pl = p0 & 3;
                const int w0 = (nf * 2 + ks) * 68 + (g * 4 + pl) * 2 + half;
                uint32_t h0, l0, h1, l1;
                split2(pbt[i * 4 + 0], pbt[i * 4 + 1], h0, l0);
                split2(pbt[i * 4 + 2], pbt[i * 4 + 3], h1, l1);
                Bh[w0] = h0; Bh[w0 + 2] = h1;
                Bl[w0] = l0; Bl[w0 + 2] = l1;
            }
        } else {
#pragma unroll
            for (int i = 0; i < 4; i++) {
                const int n = w_row + i * 32;
                const int nf = n >> 3, g = n & 7, ks = w_q >> 2;
                const int p0 = (2 * w_q) & 7, half = p0 >> 2, pl = p0 & 3;
                const int w0 = (nf * 2 + ks) * 68 + (g * 4 + pl) * 2 + half;
                uint32_t h0, l0, h1, l1;
                split2(pb[i].x, pb[i].y, h0, l0);
                split2(pb[i].z, pb[i].w, h1, l1);
                Bh[w0] = h0; Bh[w0 + 2] = h1;
                Bl[w0] = l0; Bl[w0 + 2] = l1;
            }
        }
    };

    // ---- compute one 32-k chunk: hi*hi + lo*hi + hi*lo ----
    auto compute = [&](int buf) {
        const uint32_t* Ah = sm + buf * BUF_WORDS;
        const uint32_t* Al = Ah + A_PLANE;
        const uint32_t* Bh = Ah + 2 * A_PLANE;
        const uint32_t* Bl = Bh + B_PLANE;
#pragma unroll
        for (int ks = 0; ks < 2; ks++) {
            uint32_t afh[4][4], bfh[4][2];
#pragma unroll
            for (int mf = 0; mf < 4; mf++)
                *(uint4*)afh[mf] = *(const uint4*)(Ah + ((warpM * 4 + mf) * 2 + ks) * 132 + lane * 4);
#pragma unroll
            for (int nf = 0; nf < 4; nf++)
                *(uint2*)bfh[nf] = *(const uint2*)(Bh + ((warpN * 4 + nf) * 2 + ks) * 68 + lane * 2);
#pragma unroll
            for (int mf = 0; mf < 4; mf++)
#pragma unroll
                for (int nf = 0; nf < 4; nf++)
                    mma16(acc[mf][nf], afh[mf], bfh[nf]);
#pragma unroll
            for (int mf = 0; mf < 4; mf++) {
                uint32_t t[4];
                *(uint4*)t = *(const uint4*)(Al + ((warpM * 4 + mf) * 2 + ks) * 132 + lane * 4);
#pragma unroll
                for (int nf = 0; nf < 4; nf++)
                    mma16(acc[mf][nf], t, bfh[nf]);
            }
#pragma unroll
            for (int nf = 0; nf < 4; nf++) {
                uint32_t t[2];
                *(uint2*)t = *(const uint2*)(Bl + ((warpN * 4 + nf) * 2 + ks) * 68 + lane * 2);
#pragma unroll
                for (int mf = 0; mf < 4; mf++)
                    mma16(acc[mf][nf], afh[mf], t);
            }
        }
    };

    // ---- pipelined loop: ONE barrier per chunk ----
    // sts(ch+1) targets the opposite buffer of compute(ch); the single barrier
    // orders (a) sts(ch+1) -> compute(ch+1) and (b) compute(ch) -> sts(ch+2).
    ldgA(0); ldgB(0);
    stsTile(0);
    __syncthreads();
    for (int ch = 0; ch < nch; ch++) {
        const bool more = (ch + 1 < nch);
        if (more) { ldgA(ch + 1); ldgB(ch + 1); }
        compute(ch & 1);
        if (more) {
            stsTile((ch + 1) & 1);
            __syncthreads();
        }
    }

    // ---- epilogue: direct stores ----
    const bool toutR = FUSED3 ? (opsel < 2) : TOUT;
#pragma unroll
    for (int mf = 0; mf < 4; mf++) {
        const int m = m0 + warpM * 64 + mf * 16 + g4;
        const float bv0 = BIAS ? bias[m] : 0.f;
        const float bv1 = BIAS ? bias[m + 8] : 0.f;
#pragma unroll
        for (int nf = 0; nf < 4; nf++) {
            const int n = n0 + warpN * 32 + nf * 8 + 2 * tig;
            if (toutR) {
                C[(size_t)n * ldc + m]           = acc[mf][nf][0] + bv0;
                C[(size_t)(n + 1) * ldc + m]     = acc[mf][nf][1] + bv0;
                C[(size_t)n * ldc + m + 8]       = acc[mf][nf][2] + bv1;
                C[(size_t)(n + 1) * ldc + m + 8] = acc[mf][nf][3] + bv1;
            } else {
                *(float2*)(C + (size_t)m * ldc + n) =
                    make_float2(acc[mf][nf][0] + bv0, acc[mf][nf][1] + bv0);
                *(float2*)(C + (size_t)(m + 8) * ldc + n) =
                    make_float2(acc[mf][nf][2] + bv1, acc[mf][nf][3] + bv1);
            }
        }
    }
}

// ---------------- softmax (in place over rows of W), float4 ------------------
__global__ __launch_bounds__(256) void softmax_kernel(float* __restrict__ W)
{
    float4* p4 = (float4*)(W + (size_t)blockIdx.x * NT);
    const int t = threadIdx.x;
    float4 a = p4[t], b = p4[t + 256];
    float x[8] = {a.x, a.y, a.z, a.w, b.x, b.y, b.z, b.w};

    float m = x[0];
#pragma unroll
    for (int r = 1; r < 8; r++) m = fmaxf(m, x[r]);
#pragma unroll
    for (int o = 16; o; o >>= 1) m = fmaxf(m, __shfl_xor_sync(0xffffffffu, m, o));
    __shared__ float smax[8], ssum[8];
    if ((t & 31) == 0) smax[t >> 5] = m;
    __syncthreads();
    m = smax[0];
#pragma unroll
    for (int i = 1; i < 8; i++) m = fmaxf(m, smax[i]);
    float e[8], s = 0.f;
#pragma unroll
    for (int r = 0; r < 8; r++) { e[r] = __expf(x[r] - m); s += e[r]; }
#pragma unroll
    for (int o = 16; o; o >>= 1) s += __shfl_xor_sync(0xffffffffu, s, o);
    if ((t & 31) == 0) ssum[t >> 5] = s;
    __syncthreads();
    s = ssum[0];
#pragma unroll
    for (int i = 1; i < 8; i++) s += ssum[i];
    const float inv = 1.f / s;
    p4[t]       = make_float4(e[0] * inv, e[1] * inv, e[2] * inv, e[3] * inv);
    p4[t + 256] = make_float4(e[4] * inv, e[5] * inv, e[6] * inv, e[7] * inv);
}

// ---------------- BatchNorm stats + apply ------------------------------------
__global__ __launch_bounds__(256) void bn_stats_kernel(
    const float* __restrict__ h, float* __restrict__ mean, float* __restrict__ istd)
{
    const int c = blockIdx.x;
    float s1 = 0.f, s2 = 0.f;
    for (int i = threadIdx.x; i < NB * NT; i += 256) {
        const int b = i >> 11, t = i & (NT - 1);
        const float v = h[(size_t)b * NC * NT + (size_t)c * NT + t];
        s1 += v; s2 += v * v;
    }
#pragma unroll
    for (int o = 16; o; o >>= 1) {
        s1 += __shfl_xor_sync(0xffffffffu, s1, o);
        s2 += __shfl_xor_sync(0xffffffffu, s2, o);
    }
    __shared__ float a1[8], a2[8];
    if ((threadIdx.x & 31) == 0) { a1[threadIdx.x >> 5] = s1; a2[threadIdx.x >> 5] = s2; }
    __syncthreads();
    if (threadIdx.x == 0) {
        float t1 = 0.f, t2 = 0.f;
#pragma unroll
        for (int i = 0; i < 8; i++) { t1 += a1[i]; t2 += a2[i]; }
        const float n = (float)(NB * NT);
        const float mu = t1 / n;
        const float var = t2 / n - mu * mu;
        mean[c] = mu;
        istd[c] = rsqrtf(var + 1e-5f);
    }
}

__global__ __launch_bounds__(256) void bn_apply_kernel(
    const float* __restrict__ inpt, const float* __restrict__ h,
    const float* __restrict__ gamma, const float* __restrict__ beta,
    const float* __restrict__ mean, const float* __restrict__ istd,
    float* __restrict__ out)
{
    const int i = blockIdx.x * 256 + threadIdx.x;
    const int c = (i >> 11) & (NC - 1);
    out[i] = inpt[i] + gamma[c] * ((h[i] - mean[c]) * istd[c]) + beta[c];
}

// ---------------- launch -----------------------------------------------------
extern "C" void kernel_launch(void* const* d_in, const int* in_sizes, int n_in,
                              void* d_out, int out_size)
{
    const float* inpt    = (const float*)d_in[0];
    const float* theta_w = (const float*)d_in[1];
    const float* theta_b = (const float*)d_in[2];
    const float* phi_w   = (const float*)d_in[3];
    const float* phi_b   = (const float*)d_in[4];
    const float* gw      = (const float*)d_in[5];
    const float* gb      = (const float*)d_in[6];
    const float* ht_w    = (const float*)d_in[7];
    const float* ht_b    = (const float*)d_in[8];
    const float* bn_g    = (const float*)d_in[9];
    const float* bn_b    = (const float*)d_in[10];
    float* out = (float*)d_out;

    float *p_thT, *p_phT, *p_g, *p_W, *p_atT, *p_h, *p_mean, *p_istd;
    cudaGetSymbolAddress((void**)&p_thT, g_thT);
    cudaGetSymbolAddress((void**)&p_phT, g_phT);
    cudaGetSymbolAddress((void**)&p_g,   g_g);
    cudaGetSymbolAddress((void**)&p_W,   g_W);
    cudaGetSymbolAddress((void**)&p_atT, g_atT);
    cudaGetSymbolAddress((void**)&p_h,   g_h);
    cudaGetSymbolAddress((void**)&p_mean, g_mean);
    cudaGetSymbolAddress((void**)&p_istd, g_istd);

    cudaFuncSetAttribute(tgemm<true,  true,  true,  true >, cudaFuncAttributeMaxDynamicSharedMemorySize, SMEM_BYTES);
    cudaFuncSetAttribute(tgemm<false, false, false, false>, cudaFuncAttributeMaxDynamicSharedMemorySize, SMEM_BYTES);
    cudaFuncSetAttribute(tgemm<true,  true,  false, false>, cudaFuncAttributeMaxDynamicSharedMemorySize, SMEM_BYTES);
    cudaFuncSetAttribute(tgemm<false, false, true,  false>, cudaFuncAttributeMaxDynamicSharedMemorySize, SMEM_BYTES);

    const long long sTD = (long long)NT * ND;
    const long long sDT = (long long)ND * NT;
    const long long sCT = (long long)NC * NT;
    const long long sTT = (long long)NT * NT;

    // 1) fused theta/phi/g projections: M=D, N=T, K=C; z = op*8 + b (768 CTAs)
    {
        dim3 grid(NT / 128, ND / 128, 3 * NB);
        tgemm<true, true, true, true><<<grid, 256, SMEM_BYTES>>>(
            theta_w, inpt, p_thT, theta_b,
            phi_w, p_phT, phi_b,
            gw, p_g, gb,
            NC, NC, NT, ND, 0LL, sCT, sTD);
    }

    // 2) W = thT x phT^T : M=N=T, K=D; both natural, OUT natural (T,S)
    {
        dim3 grid(NT / 128, NT / 128, NB);
        tgemm<false, false, false, false><<<grid, 256, SMEM_BYTES>>>(
            p_thT, p_phT, p_W, nullptr,
            nullptr, nullptr, nullptr, nullptr, nullptr, nullptr,
            ND, ND, ND, NT, sTD, sTD, sTT);
    }

    // 3) softmax rows of W
    softmax_kernel<<<NB * NT, 256>>>(p_W);

    // 4) attn^T = (g x P)^T : M=D, N=S, K=T; A=g natural, B=P (K,N), OUT transposed (S,D)
    {
        dim3 grid(NT / 128, ND / 128, NB);
        tgemm<true, true, false, false><<<grid, 256, SMEM_BYTES>>>(
            p_g, p_W, p_atT, nullptr,
            nullptr, nullptr, nullptr, nullptr, nullptr, nullptr,
            NT, NT, NT, ND, sDT, sTT, sTD);
    }

    // 5) h = ht_w x attn : M=C, N=T, K=D; A natural, B=attn^T natural (T,D), OUT natural (C,T)
    {
        dim3 grid(NT / 128, NC / 128, NB);
        tgemm<false, false, true, false><<<grid, 256, SMEM_BYTES>>>(
            ht_w, p_atT, p_h, ht_b,
            nullptr, nullptr, nullptr, nullptr, nullptr, nullptr,
            ND, ND, ND, NT, 0LL, sTD, sCT);
    }

    // 6) BN stats + apply with residual
    bn_stats_kernel<<<NC, 256>>>(p_h, p_mean, p_istd);
    bn_apply_kernel<<<(NB * NC * NT) / 256, 256>>>(inpt, p_h, bn_g, bn_b,
                                                   p_mean, p_istd, out);
}

// round 11
// speedup vs baseline: 1.0697x; 1.0143x over previous
#include <cuda_runtime.h>
#include <cuda_bf16.h>
#include <cstdint>
#include <math.h>

#define NB 8
#define NC 512
#define ND 256
#define NT 2048

// ---------------- scratch (device globals; no allocations allowed) ----------
__device__ float g_thT [(size_t)NB * NT * ND];   // theta^T  (B,T,D)
__device__ float g_phT [(size_t)NB * NT * ND];   // phi^T    (B,T,D)
__device__ float g_g   [(size_t)NB * ND * NT];   // g        (B,D,T)
__device__ float g_W   [(size_t)NB * NT * NT];   // W / P    (B,T,S)
__device__ float g_atT [(size_t)NB * NT * ND];   // attn^T   (B,S,D)
__device__ float g_h   [(size_t)NB * NC * NT];   // h        (B,C,T)
__device__ float g_mean[NC];
__device__ float g_istd[NC];

// ---------------- helpers ----------------------------------------------------
// bf16x3 split: x = hi + lo (each bf16 RN); packs pairs (x low half, y high half)
__device__ __forceinline__ void split2(float x, float y, uint32_t& hi, uint32_t& lo) {
    __nv_bfloat162 h = __floats2bfloat162_rn(x, y);
    float hx = __low2float(h), hy = __high2float(h);
    __nv_bfloat162 l = __floats2bfloat162_rn(x - hx, y - hy);
    hi = *reinterpret_cast<uint32_t*>(&h);
    lo = *reinterpret_cast<uint32_t*>(&l);
}

__device__ __forceinline__ void mma16(float* d, const uint32_t* a, const uint32_t* b) {
    asm volatile(
        "mma.sync.aligned.m16n8k16.row.col.f32.bf16.bf16.f32 "
        "{%0,%1,%2,%3}, {%4,%5,%6,%7}, {%8,%9}, {%0,%1,%2,%3};"
        : "+f"(d[0]), "+f"(d[1]), "+f"(d[2]), "+f"(d[3])
        : "r"(a[0]), "r"(a[1]), "r"(a[2]), "r"(a[3]), "r"(b[0]), "r"(b[1]));
}

// SMEM geometry (fragment-permuted, bf16 pair-packed uint32 words)
#define A_PLANE 2112            // 16*132 words
#define B_PLANE 2176            // 32*68 words
#define BUF_WORDS (2*A_PLANE + 2*B_PLANE)   // 8576 (Ahi, Alo, Bhi, Blo)
#define NSTAGE 3
static constexpr int SMEM_BYTES = NSTAGE * BUF_WORDS * 4;   // 102912

// ---------------- bf16x3 mma.sync batched GEMM, 3-stage pipeline -------------
// A natural (M,K) row-major.
// TB=false: B natural (N,K). TB=true: B is (K,N) (B[n][k] = Bg[k*ldb+n]).
// TOUT=false: C (M,N) ldc. TOUT=true: C[n*ldc + m]. Bias per-m.
// FUSED3: blockIdx.z = op*NB + b, op selects {A,C,bias}; op<2 -> TOUT(ldc=ND),
//         op==2 -> natural(ldc=NT). Used to fuse theta/phi/g projections.
template <bool TB, bool TOUT, bool BIAS, bool FUSED3>
__global__ __launch_bounds__(256, 2) void tgemm(
    const float* __restrict__ A, const float* __restrict__ B, float* __restrict__ C,
    const float* __restrict__ bias,
    const float* __restrict__ A1, float* __restrict__ C1, const float* __restrict__ bias1,
    const float* __restrict__ A2, float* __restrict__ C2, const float* __restrict__ bias2,
    int K, int lda, int ldb, int ldc,
    long long sA, long long sB, long long sC)
{
    extern __shared__ uint32_t sm[];
    const int tid = threadIdx.x;
    const int lane = tid & 31;
    const int wid = tid >> 5;
    const int warpM = wid >> 2, warpN = wid & 3;   // 2 x 4 warp grid
    const int g4 = lane >> 2, tig = lane & 3;

    int bz = blockIdx.z;
    int opsel = 0;
    if (FUSED3) {
        opsel = bz >> 3;       // 0:theta 1:phi 2:g
        bz &= 7;
        if (opsel == 1) { A = A1; C = C1; bias = bias1; }
        else if (opsel == 2) { A = A2; C = C2; bias = bias2; ldc = NT; }
    }
    const int m0 = blockIdx.y * 128, n0 = blockIdx.x * 128;
    A += (long long)bz * sA;
    B += (long long)bz * sB;
    C += (long long)bz * sC;

    const int w_row = tid >> 3;       // 0..31
    const int w_q   = tid & 7;        // k-quad index

    float acc[4][4][4];
#pragma unroll
    for (int a = 0; a < 4; a++)
#pragma unroll
        for (int b = 0; b < 4; b++)
#pragma unroll
            for (int c = 0; c < 4; c++) acc[a][b][c] = 0.f;

    const int nch = K >> 5;
    float4 pa[4];
    float4 pb[4];
    float  pbt[16];

    // ---- global loads into registers ----
    auto ldgA = [&](int ch) {
        const float* Ag = A + (size_t)m0 * lda + ch * 32 + w_q * 4;
#pragma unroll
        for (int i = 0; i < 4; i++)
            pa[i] = *(const float4*)(Ag + (size_t)(w_row + i * 32) * lda);
    };
    auto ldgB = [&](int ch) {
        if (TB) {
            const float* Bg = B + (size_t)(ch * 32) * ldb + n0 + (tid & 127);
            const int kq0 = tid >> 7;
#pragma unroll
            for (int i = 0; i < 4; i++) {
                const float* p = Bg + (size_t)((kq0 + 2 * i) * 4) * ldb;
                pbt[i * 4 + 0] = p[0];
                pbt[i * 4 + 1] = p[(size_t)ldb];
                pbt[i * 4 + 2] = p[2 * (size_t)ldb];
                pbt[i * 4 + 3] = p[3 * (size_t)ldb];
            }
        } else {
            const float* Bg = B + (size_t)n0 * ldb + ch * 32 + w_q * 4;
#pragma unroll
            for (int i = 0; i < 4; i++)
                pb[i] = *(const float4*)(Bg + (size_t)(w_row + i * 32) * ldb);
        }
    };

    // ---- registers -> split bf16 planes in permuted SMEM ----
    auto stsTile = [&](int buf) {
        uint32_t* Ah = sm + buf * BUF_WORDS;
        uint32_t* Al = Ah + A_PLANE;
        uint32_t* Bh = Ah + 2 * A_PLANE;
        uint32_t* Bl = Bh + B_PLANE;
#pragma unroll
        for (int i = 0; i < 4; i++) {
            const int row = w_row + i * 32;
            const int mf = row >> 4, rm = row & 15, ks = w_q >> 2;
            const int p0 = (2 * w_q) & 7, half = p0 >> 2, pl = p0 & 3;
            const int rg = half * 2 + (rm >> 3);
            const int w0 = (mf * 2 + ks) * 132 + ((rm & 7) * 4 + pl) * 4 + rg;
            uint32_t h0, l0, h1, l1;
            split2(pa[i].x, pa[i].y, h0, l0);
            split2(pa[i].z, pa[i].w, h1, l1);
            Ah[w0] = h0; Ah[w0 + 4] = h1;
            Al[w0] = l0; Al[w0 + 4] = l1;
        }
        if (TB) {
            const int n = tid & 127;
            const int kq0 = tid >> 7;
            const int nf = n >> 3, g = n & 7;
#pragma unroll
            for (int i = 0; i < 4; i++) {
                const int q = kq0 + 2 * i;
                const int ks = q >> 2, p0 = (2 * q) & 7, half = p0 >> 2, pl = p0 & 3;
                const int w0 = (nf * 2 + ks) * 68 + (g * 4 + pl) * 2 + half;
                uint32_t h0, l0, h1, l1;
                split2(pbt[i * 4 + 0], pbt[i * 4 + 1], h0, l0);
                split2(pbt[i * 4 + 2], pbt[i * 4 + 3], h1, l1);
                Bh[w0] = h0; Bh[w0 + 2] = h1;
                Bl[w0] = l0; Bl[w0 + 2] = l1;
            }
        } else {
#pragma unroll
            for (int i = 0; i < 4; i++) {
                const int n = w_row + i * 32;
                const int nf = n >> 3, g = n & 7, ks = w_q >> 2;
                const int p0 = (2 * w_q) & 7, half = p0 >> 2, pl = p0 & 3;
                const int w0 = (nf * 2 + ks) * 68 + (g * 4 + pl) * 2 + half;
                uint32_t h0, l0, h1, l1;
                split2(pb[i].x, pb[i].y, h0, l0);
                split2(pb[i].z, pb[i].w, h1, l1);
                Bh[w0] = h0; Bh[w0 + 2] = h1;
                Bl[w0] = l0; Bl[w0 + 2] = l1;
            }
        }
    };

    // ---- compute one 32-k chunk: hi*hi + lo*hi + hi*lo ----
    auto compute = [&](int buf) {
        const uint32_t* Ah = sm + buf * BUF_WORDS;
        const uint32_t* Al = Ah + A_PLANE;
        const uint32_t* Bh = Ah + 2 * A_PLANE;
        const uint32_t* Bl = Bh + B_PLANE;
#pragma unroll
        for (int ks = 0; ks < 2; ks++) {
            uint32_t afh[4][4], bfh[4][2];
#pragma unroll
            for (int mf = 0; mf < 4; mf++)
                *(uint4*)afh[mf] = *(const uint4*)(Ah + ((warpM * 4 + mf) * 2 + ks) * 132 + lane * 4);
#pragma unroll
            for (int nf = 0; nf < 4; nf++)
                *(uint2*)bfh[nf] = *(const uint2*)(Bh + ((warpN * 4 + nf) * 2 + ks) * 68 + lane * 2);
#pragma unroll
            for (int mf = 0; mf < 4; mf++)
#pragma unroll
                for (int nf = 0; nf < 4; nf++)
                    mma16(acc[mf][nf], afh[mf], bfh[nf]);
#pragma unroll
            for (int mf = 0; mf < 4; mf++) {
                uint32_t t[4];
                *(uint4*)t = *(const uint4*)(Al + ((warpM * 4 + mf) * 2 + ks) * 132 + lane * 4);
#pragma unroll
                for (int nf = 0; nf < 4; nf++)
                    mma16(acc[mf][nf], t, bfh[nf]);
            }
#pragma unroll
            for (int nf = 0; nf < 4; nf++) {
                uint32_t t[2];
                *(uint2*)t = *(const uint2*)(Bl + ((warpN * 4 + nf) * 2 + ks) * 68 + lane * 2);
#pragma unroll
                for (int mf = 0; mf < 4; mf++)
                    mma16(acc[mf][nf], afh[mf], t);
            }
        }
    };

    // ---- 3-stage pipelined loop, prefetch distance 2, ONE barrier per chunk --
    // iter ch:  STS(ch+1) [regs from LDG issued at iter ch-1] -> LDG(ch+2)
    //           -> compute(ch) -> barrier.
    // An LDG issued at iter ch is consumed by STS at iter ch+1: latency window
    // = one full compute block + barrier. Buffer reuse distance 3 makes the
    // single barrier sufficient for both RAW and WAR hazards.
    int b_sts = 1, b_cmp = 0;                 // stage indices mod 3
    ldgA(0); ldgB(0);
    stsTile(0);
    if (nch > 1) { ldgA(1); ldgB(1); }
    __syncthreads();
    for (int ch = 0; ch < nch; ch++) {
        if (ch + 1 < nch) {
            stsTile(b_sts);
            if (++b_sts == NSTAGE) b_sts = 0;
            if (ch + 2 < nch) { ldgA(ch + 2); ldgB(ch + 2); }
        }
        compute(b_cmp);
        if (++b_cmp == NSTAGE) b_cmp = 0;
        if (ch + 1 < nch) __syncthreads();
    }

    // ---- epilogue: direct stores ----
    const bool toutR = FUSED3 ? (opsel < 2) : TOUT;
#pragma unroll
    for (int mf = 0; mf < 4; mf++) {
        const int m = m0 + warpM * 64 + mf * 16 + g4;
        const float bv0 = BIAS ? bias[m] : 0.f;
        const float bv1 = BIAS ? bias[m + 8] : 0.f;
#pragma unroll
        for (int nf = 0; nf < 4; nf++) {
            const int n = n0 + warpN * 32 + nf * 8 + 2 * tig;
            if (toutR) {
                C[(size_t)n * ldc + m]           = acc[mf][nf][0] + bv0;
                C[(size_t)(n + 1) * ldc + m]     = acc[mf][nf][1] + bv0;
                C[(size_t)n * ldc + m + 8]       = acc[mf][nf][2] + bv1;
                C[(size_t)(n + 1) * ldc + m + 8] = acc[mf][nf][3] + bv1;
            } else {
                *(float2*)(C + (size_t)m * ldc + n) =
                    make_float2(acc[mf][nf][0] + bv0, acc[mf][nf][1] + bv0);
                *(float2*)(C + (size_t)(m + 8) * ldc + n) =
                    make_float2(acc[mf][nf][2] + bv1, acc[mf][nf][3] + bv1);
            }
        }
    }
}

// ---------------- softmax (in place over rows of W), float4 ------------------
__global__ __launch_bounds__(256) void softmax_kernel(float* __restrict__ W)
{
    float4* p4 = (float4*)(W + (size_t)blockIdx.x * NT);
    const int t = threadIdx.x;
    float4 a = p4[t], b = p4[t + 256];
    float x[8] = {a.x, a.y, a.z, a.w, b.x, b.y, b.z, b.w};

    float m = x[0];
#pragma unroll
    for (int r = 1; r < 8; r++) m = fmaxf(m, x[r]);
#pragma unroll
    for (int o = 16; o; o >>= 1) m = fmaxf(m, __shfl_xor_sync(0xffffffffu, m, o));
    __shared__ float smax[8], ssum[8];
    if ((t & 31) == 0) smax[t >> 5] = m;
    __syncthreads();
    m = smax[0];
#pragma unroll
    for (int i = 1; i < 8; i++) m = fmaxf(m, smax[i]);
    float e[8], s = 0.f;
#pragma unroll
    for (int r = 0; r < 8; r++) { e[r] = __expf(x[r] - m); s += e[r]; }
#pragma unroll
    for (int o = 16; o; o >>= 1) s += __shfl_xor_sync(0xffffffffu, s, o);
    if ((t & 31) == 0) ssum[t >> 5] = s;
    __syncthreads();
    s = ssum[0];
#pragma unroll
    for (int i = 1; i < 8; i++) s += ssum[i];
    const float inv = 1.f / s;
    p4[t]       = make_float4(e[0] * inv, e[1] * inv, e[2] * inv, e[3] * inv);
    p4[t + 256] = make_float4(e[4] * inv, e[5] * inv, e[6] * inv, e[7] * inv);
}

// ---------------- BatchNorm stats + apply ------------------------------------
__global__ __launch_bounds__(256) void bn_stats_kernel(
    const float* __restrict__ h, float* __restrict__ mean, float* __restrict__ istd)
{
    const int c = blockIdx.x;
    float s1 = 0.f, s2 = 0.f;
    for (int i = threadIdx.x; i < NB * NT; i += 256) {
        const int b = i >> 11, t = i & (NT - 1);
        const float v = h[(size_t)b * NC * NT + (size_t)c * NT + t];
        s1 += v; s2 += v * v;
    }
#pragma unroll
    for (int o = 16; o; o >>= 1) {
        s1 += __shfl_xor_sync(0xffffffffu, s1, o);
        s2 += __shfl_xor_sync(0xffffffffu, s2, o);
    }
    __shared__ float a1[8], a2[8];
    if ((threadIdx.x & 31) == 0) { a1[threadIdx.x >> 5] = s1; a2[threadIdx.x >> 5] = s2; }
    __syncthreads();
    if (threadIdx.x == 0) {
        float t1 = 0.f, t2 = 0.f;
#pragma unroll
        for (int i = 0; i < 8; i++) { t1 += a1[i]; t2 += a2[i]; }
        const float n = (float)(NB * NT);
        const float mu = t1 / n;
        const float var = t2 / n - mu * mu;
        mean[c] = mu;
        istd[c] = rsqrtf(var + 1e-5f);
    }
}

__global__ __launch_bounds__(256) void bn_apply_kernel(
    const float* __restrict__ inpt, const float* __restrict__ h,
    const float* __restrict__ gamma, const float* __restrict__ beta,
    const float* __restrict__ mean, const float* __restrict__ istd,
    float* __restrict__ out)
{
    const int i = blockIdx.x * 256 + threadIdx.x;
    const int c = (i >> 11) & (NC - 1);
    out[i] = inpt[i] + gamma[c] * ((h[i] - mean[c]) * istd[c]) + beta[c];
}

// ---------------- launch -----------------------------------------------------
extern "C" void kernel_launch(void* const* d_in, const int* in_sizes, int n_in,
                              void* d_out, int out_size)
{
    const float* inpt    = (const float*)d_in[0];
    const float* theta_w = (const float*)d_in[1];
    const float* theta_b = (const float*)d_in[2];
    const float* phi_w   = (const float*)d_in[3];
    const float* phi_b   = (const float*)d_in[4];
    const float* gw      = (const float*)d_in[5];
    const float* gb      = (const float*)d_in[6];
    const float* ht_w    = (const float*)d_in[7];
    const float* ht_b    = (const float*)d_in[8];
    const float* bn_g    = (const float*)d_in[9];
    const float* bn_b    = (const float*)d_in[10];
    float* out = (float*)d_out;

    float *p_thT, *p_phT, *p_g, *p_W, *p_atT, *p_h, *p_mean, *p_istd;
    cudaGetSymbolAddress((void**)&p_thT, g_thT);
    cudaGetSymbolAddress((void**)&p_phT, g_phT);
    cudaGetSymbolAddress((void**)&p_g,   g_g);
    cudaGetSymbolAddress((void**)&p_W,   g_W);
    cudaGetSymbolAddress((void**)&p_atT, g_atT);
    cudaGetSymbolAddress((void**)&p_h,   g_h);
    cudaGetSymbolAddress((void**)&p_mean, g_mean);
    cudaGetSymbolAddress((void**)&p_istd, g_istd);

    cudaFuncSetAttribute(tgemm<true,  true,  true,  true >, cudaFuncAttributeMaxDynamicSharedMemorySize, SMEM_BYTES);
    cudaFuncSetAttribute(tgemm<false, false, false, false>, cudaFuncAttributeMaxDynamicSharedMemorySize, SMEM_BYTES);
    cudaFuncSetAttribute(tgemm<true,  true,  false, false>, cudaFuncAttributeMaxDynamicSharedMemorySize, SMEM_BYTES);
    cudaFuncSetAttribute(tgemm<false, false, true,  false>, cudaFuncAttributeMaxDynamicSharedMemorySize, SMEM_BYTES);

    const long long sTD = (long long)NT * ND;
    const long long sDT = (long long)ND * NT;
    const long long sCT = (long long)NC * NT;
    const long long sTT = (long long)NT * NT;

    // 1) fused theta/phi/g projections: M=D, N=T, K=C; z = op*8 + b (768 CTAs)
    {
        dim3 grid(NT / 128, ND / 128, 3 * NB);
        tgemm<true, true, true, true><<<grid, 256, SMEM_BYTES>>>(
            theta_w, inpt, p_thT, theta_b,
            phi_w, p_phT, phi_b,
            gw, p_g, gb,
            NC, NC, NT, ND, 0LL, sCT, sTD);
    }

    // 2) W = thT x phT^T : M=N=T, K=D; both natural, OUT natural (T,S)
    {
        dim3 grid(NT / 128, NT / 128, NB);
        tgemm<false, false, false, false><<<grid, 256, SMEM_BYTES>>>(
            p_thT, p_phT, p_W, nullptr,
            nullptr, nullptr, nullptr, nullptr, nullptr, nullptr,
            ND, ND, ND, NT, sTD, sTD, sTT);
    }

    // 3) softmax rows of W
    softmax_kernel<<<NB * NT, 256>>>(p_W);

    // 4) attn^T = (g x P)^T : M=D, N=S, K=T; A=g natural, B=P (K,N), OUT transposed (S,D)
    {
        dim3 grid(NT / 128, ND / 128, NB);
        tgemm<true, true, false, false><<<grid, 256, SMEM_BYTES>>>(
            p_g, p_W, p_atT, nullptr,
            nullptr, nullptr, nullptr, nullptr, nullptr, nullptr,
            NT, NT, NT, ND, sDT, sTT, sTD);
    }

    // 5) h = ht_w x attn : M=C, N=T, K=D; A natural, B=attn^T natural (T,D), OUT natural (C,T)
    {
        dim3 grid(NT / 128, NC / 128, NB);
        tgemm<false, false, true, false><<<grid, 256, SMEM_BYTES>>>(
            ht_w, p_atT, p_h, ht_b,
            nullptr, nullptr, nullptr, nullptr, nullptr, nullptr,
            ND, ND, ND, NT, 0LL, sTD, sCT);
    }

    // 6) BN stats + apply with residual
    bn_stats_kernel<<<NC, 256>>>(p_h, p_mean, p_istd);
    bn_apply_kernel<<<(NB * NC * NT) / 256, 256>>>(inpt, p_h, bn_g, bn_b,
                                                   p_mean, p_istd, out);
}